// round 9
// baseline (speedup 1.0000x reference)
#include <cuda_runtime.h>

#define N_PATHS   8
#define N_FEAT    128
#define CART      3
#define N_SPECIES 10
#define ROW_F4    1024          // 4096 floats per x row = 1024 float4
#define OUT_F4    96            // 384 floats per out row = 96 float4
#define TPB       288           // 9 warps = 3 atom-slots of 96 lanes
#define SLOTS     3             // atoms per work unit
#define LPA       96            // lanes per atom (3 full warps per atom)

// dynamic work queue state (self-resetting; zero-init on module load)
__device__ unsigned g_next = 0;
__device__ unsigned g_done = 0;

__global__ __launch_bounds__(TPB, 7)
void wps_kernel(const float4* __restrict__ x,
                const float*  __restrict__ y,
                const float*  __restrict__ w,
                float4* __restrict__ out,
                int n_atoms,
                unsigned n_units)
{
    __shared__ unsigned s_next[2];   // double-buffered prefetched unit index

    const int slot = threadIdx.x / LPA;    // 0..2 : which atom in the unit
    const int lane = threadIdx.x % LPA;    // 0..95: which float4 of the output
    const int wl   = threadIdx.x & 31;     // lane within warp

    // the 4 output elements e = 4*lane .. 4*lane+3 span exactly 2 features
    const int e0 = lane * 4;
    const int f0 = e0 / CART;              // first feature
    const int r  = e0 - f0 * CART;         // e0 % 3, fixed per thread

    // first claim
    if (threadIdx.x == 0) s_next[0] = atomicAdd(&g_next, 1u);
    __syncthreads();
    unsigned cur = s_next[0];
    int p = 1;

    while (cur < n_units) {
        // prefetch the next unit (thread 0), overlapped with processing
        if (threadIdx.x == 0) s_next[p] = atomicAdd(&g_next, 1u);

        const int a = (int)(cur * SLOTS) + slot;
        if (a < n_atoms) {
            // ---- species via warp ballot: warp lies entirely in one atom ----
            const float* yrow = y + (size_t)a * N_SPECIES;
            float yv = (wl < N_SPECIES) ? __ldg(&yrow[wl]) : 0.0f;
            unsigned m = __ballot_sync(0xffffffffu, yv > 0.5f);
            const int s = __ffs(m) - 1;

            const float*  wsp  = w + s * (N_PATHS * N_FEAT) + f0;  // 40 KB, L1-resident
            const float4* xrow = x + (size_t)a * ROW_F4;

            float4 acc = {0.f, 0.f, 0.f, 0.f};
            #pragma unroll
            for (int q = 0; q < N_PATHS; ++q) {
                float4 xv = __ldcs(&xrow[q * LPA + lane]);   // streaming read-once
                float wa = __ldg(&wsp[q * N_FEAT]);
                float wb = __ldg(&wsp[q * N_FEAT + 1]);
                // r=0: (wa,wa,wa,wb)  r=1: (wa,wa,wb,wb)  r=2: (wa,wb,wb,wb)
                float wy = (r == 2) ? wb : wa;
                float wz = (r == 0) ? wa : wb;
                acc.x = fmaf(xv.x, wa, acc.x);
                acc.y = fmaf(xv.y, wy, acc.y);
                acc.z = fmaf(xv.z, wz, acc.z);
                acc.w = fmaf(xv.w, wb, acc.w);
            }

            __stcs(&out[(size_t)a * OUT_F4 + lane], acc);
        }

        __syncthreads();          // s_next[p] write visible; prior-slot reads done
        cur = s_next[p];
        p ^= 1;
    }

    // ---- self-reset protocol: last CTA to finish zeroes the queue ----
    if (threadIdx.x == 0) {
        __threadfence();
        unsigned d = atomicAdd(&g_done, 1u);
        if (d == gridDim.x - 1) {
            g_next = 0;
            g_done = 0;
            __threadfence();
        }
    }
}

extern "C" void kernel_launch(void* const* d_in, const int* in_sizes, int n_in,
                              void* d_out, int out_size)
{
    const float4* x = (const float4*)d_in[0];   // [N, 4096] fp32
    const float*  y = (const float*) d_in[1];   // [N, 10] one-hot
    const float*  w = (const float*) d_in[2];   // [10, 8, 128] fp32
    float4* out = (float4*)d_out;               // [N, 384] fp32

    const int n_atoms = in_sizes[0] / 4096;
    const unsigned n_units = (unsigned)((n_atoms + SLOTS - 1) / SLOTS);

    unsigned grid = 148 * 7;                     // 7 CTAs/SM, 63 warps/SM
    if (grid > n_units) grid = n_units;

    wps_kernel<<<grid, TPB>>>(x, y, w, out, n_atoms, n_units);
}